// round 7
// baseline (speedup 1.0000x reference)
#include <cuda_runtime.h>
#include <cuda_bf16.h>

// Sparsemax along last axis. Input (4,4096,4096) fp32 -> 16384 rows of D=4096.
// One CTA per row; row register-resident (256 thr x 16 floats).
// theta (= rowmax + tau) found by: max-reduce -> 4-threshold relu-sum probe ->
// Michelot/Newton fixed point  theta' = (sum_{v>theta} v - 1) / K.
// Every reduction round: warp shfl-reduce, ONE __syncthreads, then all threads
// redundantly combine the 8 warp partials from smem (double-buffered for WAR).

#define D      4096
#define NTHR   256
#define V4     4

__global__ __launch_bounds__(NTHR)
void sparsemax_kernel(const float* __restrict__ in, float* __restrict__ out) {
    __shared__ float s_max[8];
    __shared__ float s_g[4][8];     // probe partials
    __shared__ float s_s[2][8];     // Newton sum partials (double buffered)
    __shared__ float s_c[2][8];     // Newton count partials

    const size_t base = (size_t)blockIdx.x * D;
    const float4* rp = reinterpret_cast<const float4*>(in + base);
    float4*       wp = reinterpret_cast<float4*>(out + base);
    const int t    = threadIdx.x;
    const int lane = t & 31;
    const int warp = t >> 5;

    float4 v[V4];
#pragma unroll
    for (int j = 0; j < V4; ++j) v[j] = rp[t + NTHR * j];

    // ---- round 1: row max (1 barrier) ----
    float m = v[0].x;
#pragma unroll
    for (int j = 0; j < V4; ++j)
        m = fmaxf(m, fmaxf(fmaxf(v[j].x, v[j].y), fmaxf(v[j].z, v[j].w)));
#pragma unroll
    for (int o = 16; o > 0; o >>= 1) m = fmaxf(m, __shfl_xor_sync(0xffffffffu, m, o));
    if (lane == 0) s_max[warp] = m;
    __syncthreads();
    m = s_max[0];
#pragma unroll
    for (int w = 1; w < 8; ++w) m = fmaxf(m, s_max[w]);

    // ---- round 2: probe g(theta)=sum relu(v-theta) at theta = m - off (1 barrier) ----
    // off[0]=1 guarantees g >= relu(max - (m-1)) = 1, so a valid start always exists.
    const float off0 = 1.0f, off1 = 0.5f, off2 = 0.25f, off3 = 0.125f;
    float g0 = 0.f, g1 = 0.f, g2 = 0.f, g3 = 0.f;
#pragma unroll
    for (int j = 0; j < V4; ++j) {
        const float e[4] = { v[j].x - m, v[j].y - m, v[j].z - m, v[j].w - m };
#pragma unroll
        for (int q = 0; q < 4; ++q) {
            g0 += fmaxf(e[q] + off0, 0.0f);
            g1 += fmaxf(e[q] + off1, 0.0f);
            g2 += fmaxf(e[q] + off2, 0.0f);
            g3 += fmaxf(e[q] + off3, 0.0f);
        }
    }
#pragma unroll
    for (int o = 16; o > 0; o >>= 1) {
        g0 += __shfl_xor_sync(0xffffffffu, g0, o);
        g1 += __shfl_xor_sync(0xffffffffu, g1, o);
        g2 += __shfl_xor_sync(0xffffffffu, g2, o);
        g3 += __shfl_xor_sync(0xffffffffu, g3, o);
    }
    if (lane == 0) { s_g[0][warp] = g0; s_g[1][warp] = g1; s_g[2][warp] = g2; s_g[3][warp] = g3; }
    __syncthreads();
    float G0 = 0.f, G1 = 0.f, G2 = 0.f, G3 = 0.f;
#pragma unroll
    for (int w = 0; w < 8; ++w) {
        G0 += s_g[0][w]; G1 += s_g[1][w]; G2 += s_g[2][w]; G3 += s_g[3][w];
    }
    // largest theta (smallest offset) still satisfying g >= 1 -> theta <= theta*
    float theta = m - off0;
    if (G1 >= 1.0f) theta = m - off1;
    if (G2 >= 1.0f) theta = m - off2;
    if (G3 >= 1.0f) theta = m - off3;

    // ---- Newton/Michelot: theta' = (S - 1)/K over {v > theta} (1 barrier/iter) ----
#pragma unroll 1
    for (int it = 0; it < 24; ++it) {
        const int p = it & 1;
        float s = 0.0f, c = 0.0f;
#pragma unroll
        for (int j = 0; j < V4; ++j) {
            if (v[j].x > theta) { s += v[j].x; c += 1.0f; }
            if (v[j].y > theta) { s += v[j].y; c += 1.0f; }
            if (v[j].z > theta) { s += v[j].z; c += 1.0f; }
            if (v[j].w > theta) { s += v[j].w; c += 1.0f; }
        }
#pragma unroll
        for (int o = 16; o > 0; o >>= 1) {
            s += __shfl_xor_sync(0xffffffffu, s, o);
            c += __shfl_xor_sync(0xffffffffu, c, o);
        }
        if (lane == 0) { s_s[p][warp] = s; s_c[p][warp] = c; }
        __syncthreads();
        float S = 0.0f, C = 0.0f;
#pragma unroll
        for (int w = 0; w < 8; ++w) { S += s_s[p][w]; C += s_c[p][w]; }
        const float nth = (S - 1.0f) / C;   // C >= 1: max always in support
        if (nth == theta) break;            // identical in all threads (same smem inputs)
        theta = nth;
    }

    // ---- emit p = max(v - theta, 0) ----
#pragma unroll
    for (int j = 0; j < V4; ++j) {
        float4 o;
        o.x = fmaxf(v[j].x - theta, 0.0f);
        o.y = fmaxf(v[j].y - theta, 0.0f);
        o.z = fmaxf(v[j].z - theta, 0.0f);
        o.w = fmaxf(v[j].w - theta, 0.0f);
        wp[t + NTHR * j] = o;
    }
}

extern "C" void kernel_launch(void* const* d_in, const int* in_sizes, int n_in,
                              void* d_out, int out_size) {
    const float* in = (const float*)d_in[0];
    float* out = (float*)d_out;
    const int rows = in_sizes[0] / D;   // 16384
    sparsemax_kernel<<<rows, NTHR>>>(in, out);
}

// round 10
// speedup vs baseline: 1.3630x; 1.3630x over previous
#include <cuda_runtime.h>
#include <cuda_bf16.h>

// Sparsemax along last axis. Input (4,4096,4096) fp32 -> 16384 rows of D=4096.
// One CTA per row; row register-resident (256 thr x 16 floats).
// Phase 1: (max, 2nd-max) reduce -> start theta0 = 0.5*(m + m2 - 1)  [g(theta0) >= 1 provable]
// Phase 2: Michelot/Newton fixed point theta' = (sum_{v>theta} v - 1) / count.
// Reductions: warp shfl + two barriers with warp0-only second stage
// (idle warps cost no issue slots - this kernel is issue-bound, R7 evidence).

#define D      4096
#define NTHR   256
#define V4     4

__global__ void __launch_bounds__(NTHR, 7)
sparsemax_kernel(const float* __restrict__ in, float* __restrict__ out) {
    __shared__ float s_m[8];
    __shared__ float s_m2[8];
    __shared__ float s_s[8];
    __shared__ float s_c[8];
    __shared__ float s_b[2];

    const size_t base = (size_t)blockIdx.x * D;
    const float4* rp = reinterpret_cast<const float4*>(in + base);
    float4*       wp = reinterpret_cast<float4*>(out + base);
    const int t    = threadIdx.x;
    const int lane = t & 31;
    const int warp = t >> 5;

    float4 v[V4];
#pragma unroll
    for (int j = 0; j < V4; ++j) v[j] = rp[t + NTHR * j];

    // ---- phase 1: (max, second max) ----
    const float NEG = -3.402823466e+38f;
    float m = NEG, m2 = NEG;
#pragma unroll
    for (int j = 0; j < V4; ++j) {
        float x;
        x = v[j].x; m2 = fmaxf(m2, fminf(m, x)); m = fmaxf(m, x);
        x = v[j].y; m2 = fmaxf(m2, fminf(m, x)); m = fmaxf(m, x);
        x = v[j].z; m2 = fmaxf(m2, fminf(m, x)); m = fmaxf(m, x);
        x = v[j].w; m2 = fmaxf(m2, fminf(m, x)); m = fmaxf(m, x);
    }
#pragma unroll
    for (int o = 16; o > 0; o >>= 1) {
        const float M  = __shfl_xor_sync(0xffffffffu, m,  o);
        const float M2 = __shfl_xor_sync(0xffffffffu, m2, o);
        m2 = fmaxf(fmaxf(m2, M2), fminf(m, M));
        m  = fmaxf(m, M);
    }
    if (lane == 0) { s_m[warp] = m; s_m2[warp] = m2; }
    __syncthreads();
    m = s_m[0]; m2 = s_m2[0];
#pragma unroll
    for (int w = 1; w < 8; ++w) {
        const float M = s_m[w], M2 = s_m2[w];
        m2 = fmaxf(fmaxf(m2, M2), fminf(m, M));
        m  = fmaxf(m, M);
    }
    // theta0 = m - x, x = 0.5*(1 + (m - m2)); valid start for any gap (g(theta0) >= 1)
    float theta = 0.5f * (m + m2 - 1.0f);

    // ---- phase 2: Newton/Michelot, R3-style 2-barrier asymmetric reduction ----
#pragma unroll 1
    for (int it = 0; it < 24; ++it) {
        float s = 0.0f, c = 0.0f;
#pragma unroll
        for (int j = 0; j < V4; ++j) {
            if (v[j].x > theta) { s += v[j].x; c += 1.0f; }
            if (v[j].y > theta) { s += v[j].y; c += 1.0f; }
            if (v[j].z > theta) { s += v[j].z; c += 1.0f; }
            if (v[j].w > theta) { s += v[j].w; c += 1.0f; }
        }
#pragma unroll
        for (int o = 16; o > 0; o >>= 1) {
            s += __shfl_xor_sync(0xffffffffu, s, o);
            c += __shfl_xor_sync(0xffffffffu, c, o);
        }
        if (lane == 0) { s_s[warp] = s; s_c[warp] = c; }
        __syncthreads();
        if (warp == 0) {
            float ss = s_s[lane & 7];
            float cc = s_c[lane & 7];
#pragma unroll
            for (int o = 4; o > 0; o >>= 1) {
                ss += __shfl_xor_sync(0xffffffffu, ss, o);
                cc += __shfl_xor_sync(0xffffffffu, cc, o);
            }
            if (lane == 0) { s_b[0] = ss; s_b[1] = cc; }
        }
        __syncthreads();
        const float S = s_b[0];
        const float C = s_b[1];            // C >= 1: max always in support
        const float nth = (S - 1.0f) / C;
        if (nth == theta) break;           // uniform decision (same smem inputs everywhere)
        theta = nth;
    }

    // ---- emit p = max(v - theta, 0) ----
#pragma unroll
    for (int j = 0; j < V4; ++j) {
        float4 o;
        o.x = fmaxf(v[j].x - theta, 0.0f);
        o.y = fmaxf(v[j].y - theta, 0.0f);
        o.z = fmaxf(v[j].z - theta, 0.0f);
        o.w = fmaxf(v[j].w - theta, 0.0f);
        wp[t + NTHR * j] = o;
    }
}

extern "C" void kernel_launch(void* const* d_in, const int* in_sizes, int n_in,
                              void* d_out, int out_size) {
    const float* in = (const float*)d_in[0];
    float* out = (float*)d_out;
    const int rows = in_sizes[0] / D;   // 16384
    sparsemax_kernel<<<rows, NTHR>>>(in, out);
}